// round 3
// baseline (speedup 1.0000x reference)
#include <cuda_runtime.h>
#include <cstdint>

// ---------------------------------------------------------------------------
// SE block, fused persistent kernel.
// x: [32, 512, 56, 56] fp32.  Chunk = 8 batches = 8*512 slices = 51.4 MB.
// Per chunk: reduce (squeeze) -> grid barrier -> per-block hid -> scale.
// Chunk x stays L2-resident between reduce and scale => second read is L2.
// ---------------------------------------------------------------------------

#define C         512
#define CR        32
#define SPATIAL4  784          // 56*56/4 float4 per slice
#define CHUNK_B   8
#define NCHUNK    4
#define CHUNK_SLICES (CHUNK_B * C)   // 4096

__device__ float d_sq[32 * C];

// --- software grid barrier (generation-based; state self-restoring) --------
__device__ unsigned int g_count = 0;
__device__ unsigned int g_gen   = 0;

__device__ __forceinline__ void grid_sync(unsigned int nblocks) {
    __syncthreads();
    if (threadIdx.x == 0) {
        __threadfence();
        unsigned int gen    = atomicAdd(&g_gen, 0u);
        unsigned int ticket = atomicAdd(&g_count, 1u);
        if (ticket == nblocks - 1u) {
            atomicExch(&g_count, 0u);
            __threadfence();
            atomicAdd(&g_gen, 1u);
        } else {
            while (atomicAdd(&g_gen, 0u) == gen) { __nanosleep(64); }
        }
        __threadfence();
    }
    __syncthreads();
}

__global__ __launch_bounds__(1024, 1) void se_fused(
    const float* __restrict__ x,
    const float* __restrict__ w1,
    const float* __restrict__ b1,
    const float* __restrict__ w2,
    const float* __restrict__ b2,
    float* __restrict__ out,
    unsigned int nblocks)
{
    const int tid   = threadIdx.x;
    const int lane  = tid & 31;
    const int gwarp = blockIdx.x * 32 + (tid >> 5);
    const int total_warps = (int)nblocks * 32;

    const float4* __restrict__ x4 = reinterpret_cast<const float4*>(x);
    float4*       __restrict__ o4 = reinterpret_cast<float4*>(out);

    __shared__ float hid_s[CHUNK_B * CR];   // 256 floats

    for (int ck = 0; ck < NCHUNK; ++ck) {
        const int    batch0 = ck * CHUNK_B;
        const size_t slice0 = (size_t)batch0 * C;

        // ---------------- Phase A: squeeze (mean) per slice ----------------
        for (int s = gwarp; s < CHUNK_SLICES; s += total_warps) {
            const float4* __restrict__ p = x4 + (slice0 + s) * SPATIAL4;
            float acc = 0.0f;
            // 784 = 24*32 + 16 ; 3 groups of 8 batched loads
            #pragma unroll
            for (int g = 0; g < 3; ++g) {
                float4 v[8];
                #pragma unroll
                for (int i = 0; i < 8; ++i)
                    v[i] = p[lane + 32 * (g * 8 + i)];
                #pragma unroll
                for (int i = 0; i < 8; ++i)
                    acc += (v[i].x + v[i].y) + (v[i].z + v[i].w);
            }
            if (lane < 16) {
                float4 v = p[768 + lane];
                acc += (v.x + v.y) + (v.z + v.w);
            }
            #pragma unroll
            for (int off = 16; off > 0; off >>= 1)
                acc += __shfl_down_sync(0xFFFFFFFFu, acc, off);
            if (lane == 0)
                d_sq[slice0 + s] = acc * (1.0f / 3136.0f);
        }

        grid_sync(nblocks);

        // ------- hid[b][j] = relu(sq[b] . w1[j] + b1[j]), per-block -------
        if (tid < CHUNK_B * CR) {
            const int bl = tid >> 5;       // local batch 0..7
            const int j  = tid & 31;       // hidden unit
            const float4* __restrict__ sq4 =
                reinterpret_cast<const float4*>(d_sq + (size_t)(batch0 + bl) * C);
            const float4* __restrict__ w14 =
                reinterpret_cast<const float4*>(w1 + j * C);
            float a0 = 0.f, a1 = 0.f, a2 = 0.f, a3 = 0.f;
            #pragma unroll 4
            for (int i = 0; i < C / 4; ++i) {
                float4 sv = sq4[i];
                float4 wv = w14[i];
                a0 = fmaf(sv.x, wv.x, a0);
                a1 = fmaf(sv.y, wv.y, a1);
                a2 = fmaf(sv.z, wv.z, a2);
                a3 = fmaf(sv.w, wv.w, a3);
            }
            hid_s[tid] = fmaxf((a0 + a1) + (a2 + a3) + b1[j], 0.0f);
        }
        __syncthreads();

        // ---------------- Phase B: scale (x * sigmoid(fc2)) ----------------
        for (int s = gwarp; s < CHUNK_SLICES; s += total_warps) {
            const int bl = s >> 9;         // local batch
            const int ch = s & (C - 1);    // channel
            const float* __restrict__ hb  = hid_s + bl * CR;
            const float* __restrict__ w2r = w2 + ch * CR;
            float acc = b2[ch];
            #pragma unroll
            for (int j = 0; j < CR; ++j)
                acc = fmaf(hb[j], w2r[j], acc);
            const float e = 1.0f / (1.0f + __expf(-acc));

            const float4* __restrict__ p = x4 + (slice0 + s) * SPATIAL4;
            float4*       __restrict__ q = o4 + (slice0 + s) * SPATIAL4;
            #pragma unroll
            for (int g = 0; g < 3; ++g) {
                float4 v[8];
                #pragma unroll
                for (int i = 0; i < 8; ++i)
                    v[i] = __ldcs(p + lane + 32 * (g * 8 + i));
                #pragma unroll
                for (int i = 0; i < 8; ++i) {
                    float4 r = v[i];
                    r.x *= e; r.y *= e; r.z *= e; r.w *= e;
                    __stcs(q + lane + 32 * (g * 8 + i), r);
                }
            }
            if (lane < 16) {
                float4 v = __ldcs(p + 768 + lane);
                v.x *= e; v.y *= e; v.z *= e; v.w *= e;
                __stcs(q + 768 + lane, v);
            }
        }
        // next chunk's hid_s write is gated by its grid_sync's __syncthreads
    }
}

// ---------------------------------------------------------------------------
extern "C" void kernel_launch(void* const* d_in, const int* in_sizes, int n_in,
                              void* d_out, int out_size) {
    const float* x  = (const float*)d_in[0];
    const float* w1 = (const float*)d_in[1];
    const float* b1 = (const float*)d_in[2];
    const float* w2 = (const float*)d_in[3];
    const float* b2 = (const float*)d_in[4];
    float* out = (float*)d_out;

    int dev = 0;
    cudaGetDevice(&dev);
    int nsm = 0;
    cudaDeviceGetAttribute(&nsm, cudaDevAttrMultiProcessorCount, dev);
    if (nsm <= 0) nsm = 148;

    se_fused<<<nsm, 1024>>>(x, w1, b1, w2, b2, out, (unsigned int)nsm);
}